// round 15
// baseline (speedup 1.0000x reference)
#include <cuda_runtime.h>
#include <math.h>

// ---------------------------------------------------------------------------
// AdaFaceLoss, single fused persistent kernel, R8 core + END-TAPERED chunks:
//  - loop 1: tickets [0,9600) = 20KB chunks (rows 0..479, 20/row) — byte-
//    identical to the proven R8 hot loop (exit test vs NBIG).
//  - loop 2: tickets [9600,11200) = 8KB chunks (rows 480..511, 50/row) —
//    entered only when big tickets are exhausted; same counter, prefetch
//    carries across. Drain stagger drops ~4us -> ~1.5us.
//  - block 0 runs the preamble first (norm stats, label gathers, margin
//    trig); stealing absorbs its head start.
//  - join: fence + atomicAdd(g_done); last block runs the finish tail.
// Labels are int32 (JAX x64-disabled downgrades the int64 request).
// ---------------------------------------------------------------------------

#define B_ROWS 512
#define C_COLS 100000
#define F4_BIG 1250                  // 20KB
#define F4_SMALL 500                 // 8KB
#define ROWS_BIG 480
#define NBIG (ROWS_BIG * 20)         // 9600
#define NSMALL ((B_ROWS - ROWS_BIG) * 50)   // 1600
#define NTICK (NBIG + NSMALL)        // 11200
#define BIG_TOTAL_F4 (NBIG * F4_BIG) // 12,000,000
#define THREADS 256
#define GRID_MAIN 1216               // 152 SMs * 8

// exp(64*x) = 2^(K*x), K = 64*log2(e)
#define KLOG2 92.33248261689366f
#define MAGICF 12582912.0f           // 1.5 * 2^23
#define PC0 1.0f
#define PC1 0.6931471805599453f
#define PC2 0.2402265069591007f
#define PC3 0.05550410866482158f
#define PC4 0.009618129107628477f

__device__ float g_pA[NBIG];
__device__ float g_pB[NSMALL];
__device__ float g_corr[B_ROWS];
__device__ float g_smod[B_ROWS];
__device__ unsigned g_ticket;        // reset by last block
__device__ unsigned g_done;          // reset by last block

typedef unsigned long long u64;

// ---- packed f32x2 helpers (sm_103a) ----
__device__ __forceinline__ u64 pk2(float a, float b) {
    u64 r; asm("mov.b64 %0,{%1,%2};" : "=l"(r) : "f"(a), "f"(b)); return r;
}
__device__ __forceinline__ u64 mul2(u64 a, u64 b) {
    u64 r; asm("mul.rn.f32x2 %0,%1,%2;" : "=l"(r) : "l"(a), "l"(b)); return r;
}
__device__ __forceinline__ u64 add2(u64 a, u64 b) {
    u64 r; asm("add.rn.f32x2 %0,%1,%2;" : "=l"(r) : "l"(a), "l"(b)); return r;
}
__device__ __forceinline__ u64 fma2(u64 a, u64 b, u64 c) {
    u64 r; asm("fma.rn.f32x2 %0,%1,%2,%3;" : "=l"(r) : "l"(a), "l"(b), "l"(c)); return r;
}

// Scalar replica — bitwise-identical op sequence to the packed fast-exp so
// the label-column term cancels exactly.
__device__ __forceinline__ float fast_exp_scalar(float x) {
    float t = __fmul_rn(x, KLOG2);
    float z = __fadd_rn(t, MAGICF);
    float zn = __fmaf_rn(z, -1.0f, MAGICF);
    float f = __fmaf_rn(x, KLOG2, zn);
    float p = __fmaf_rn(PC4, f, PC3);
    p = __fmaf_rn(p, f, PC2);
    p = __fmaf_rn(p, f, PC1);
    p = __fmaf_rn(p, f, PC0);
    unsigned zi = __float_as_uint(z);
    return __uint_as_float(__float_as_uint(p) + (zi << 23));
}

__device__ __forceinline__ void exp_pack_acc(u64 x, u64 K2, u64 M2, u64 N1,
                                             u64 C42, u64 C32, u64 C22, u64 C12, u64 C02,
                                             float& a0, float& a1) {
    u64 t = mul2(x, K2);
    u64 z = add2(t, M2);
    u64 zn = fma2(z, N1, M2);        // -round(t)
    u64 f = fma2(x, K2, zn);
    u64 p = fma2(C42, f, C32);
    p = fma2(p, f, C22);
    p = fma2(p, f, C12);
    p = fma2(p, f, C02);
    unsigned zl = (unsigned)z, zh = (unsigned)(z >> 32);
    unsigned pl = (unsigned)p, ph = (unsigned)(p >> 32);
    a0 += __uint_as_float(pl + (zl << 23));
    a1 += __uint_as_float(ph + (zh << 23));
}

// block-wide sum over 256 threads; result broadcast
__device__ __forceinline__ float block_sum_256(float v, float* red) {
    #pragma unroll
    for (int o = 16; o > 0; o >>= 1)
        v += __shfl_down_sync(0xffffffffu, v, o);
    const int w = threadIdx.x >> 5;
    const int l = threadIdx.x & 31;
    if (l == 0) red[w] = v;
    __syncthreads();
    float t = 0.f;
    if (w == 0) {
        t = (l < 8) ? red[l] : 0.f;
        #pragma unroll
        for (int o = 4; o > 0; o >>= 1)
            t += __shfl_down_sync(0xffffffffu, t, o);
        if (l == 0) red[0] = t;
    }
    __syncthreads();
    float r = red[0];
    __syncthreads();
    return r;
}

__global__ __launch_bounds__(THREADS)
void fused_kernel(const float* __restrict__ logits,
                  const float* __restrict__ norms,
                  const int* __restrict__ labels,
                  float* __restrict__ out) {
    __shared__ float sh[8];
    __shared__ unsigned sh_tk[2];
    __shared__ unsigned sh_last;
    const int tid = threadIdx.x;
    const int warp = tid >> 5;
    const int lane = tid & 31;

    // ---------------- block 0: preamble, concurrent with streaming --------
    if (blockIdx.x == 0) {
        const int r0 = tid, r1 = tid + 256;
        int lab0 = labels[r0]; lab0 = max(0, min(lab0, C_COLS - 1));
        int lab1 = labels[r1]; lab1 = max(0, min(lab1, C_COLS - 1));
        const float x0 = __ldg(logits + (size_t)r0 * C_COLS + lab0);
        const float x1 = __ldg(logits + (size_t)r1 * C_COLS + lab1);

        float n0 = fminf(fmaxf(norms[r0], 0.001f), 100.0f);
        float n1 = fminf(fmaxf(norms[r1], 0.001f), 100.0f);
        float mean = block_sum_256(n0 + n1, sh) * (1.0f / 512.0f);
        float d0 = n0 - mean, d1 = n1 - mean;
        float var = block_sum_256(d0 * d0 + d1 * d1, sh) * (1.0f / 511.0f);
        float inv = 0.333f / (sqrtf(var) + 1e-6f);

        float ms0 = fminf(fmaxf((n0 - mean) * inv, -1.0f), 1.0f);
        float ms1 = fminf(fmaxf((n1 - mean) * inv, -1.0f), 1.0f);

        const float PI_EPS = 3.14159265358979323846f - 1e-6f;

        float c0 = fminf(fmaxf(x0, -1.0f + 1e-6f), 1.0f - 1e-6f);
        float th0 = fminf(fmaxf(acosf(c0) - 0.4f * ms0, 1e-6f), PI_EPS);
        float smod0 = (cosf(th0) - (0.4f + 0.4f * ms0)) * 64.0f;
        g_smod[r0] = smod0;
        g_corr[r0] = expf(smod0) - fast_exp_scalar(x0);

        float c1 = fminf(fmaxf(x1, -1.0f + 1e-6f), 1.0f - 1e-6f);
        float th1 = fminf(fmaxf(acosf(c1) - 0.4f * ms1, 1e-6f), PI_EPS);
        float smod1 = (cosf(th1) - (0.4f + 0.4f * ms1)) * 64.0f;
        g_smod[r1] = smod1;
        g_corr[r1] = expf(smod1) - fast_exp_scalar(x1);
        __syncthreads();
    }

    // ---------------- loop 1: big chunks (R8 hot loop, exit vs NBIG) ------
    const u64 K2 = pk2(KLOG2, KLOG2);
    const u64 M2 = pk2(MAGICF, MAGICF);
    const u64 N1 = pk2(-1.0f, -1.0f);
    const u64 C42 = pk2(PC4, PC4);
    const u64 C32 = pk2(PC3, PC3);
    const u64 C22 = pk2(PC2, PC2);
    const u64 C12 = pk2(PC1, PC1);
    const u64 C02 = pk2(PC0, PC0);

    if (tid == 0) sh_tk[0] = atomicAdd(&g_ticket, 1u);
    __syncthreads();

    const bool has5 = (tid + 1024) < F4_BIG;     // tid < 226
    const bool has2s = (tid + 256) < F4_SMALL;   // tid < 244

    int p = 0;
    while (true) {
        const unsigned c = sh_tk[p];
        if (c >= NBIG) break;
        if (tid == 0) sh_tk[p ^ 1] = atomicAdd(&g_ticket, 1u);

        const ulonglong2* __restrict__ base =
            (const ulonglong2*)logits + (size_t)c * F4_BIG;

        ulonglong2 v0 = base[tid];
        ulonglong2 v1 = base[tid + 256];
        ulonglong2 v2 = base[tid + 512];
        ulonglong2 v3 = base[tid + 768];
        ulonglong2 v4;
        if (has5) v4 = base[tid + 1024];

        float s0 = 0.f, s1 = 0.f, s2 = 0.f, s3 = 0.f;
        exp_pack_acc(v0.x, K2, M2, N1, C42, C32, C22, C12, C02, s0, s1);
        exp_pack_acc(v0.y, K2, M2, N1, C42, C32, C22, C12, C02, s2, s3);
        exp_pack_acc(v1.x, K2, M2, N1, C42, C32, C22, C12, C02, s0, s1);
        exp_pack_acc(v1.y, K2, M2, N1, C42, C32, C22, C12, C02, s2, s3);
        exp_pack_acc(v2.x, K2, M2, N1, C42, C32, C22, C12, C02, s0, s1);
        exp_pack_acc(v2.y, K2, M2, N1, C42, C32, C22, C12, C02, s2, s3);
        exp_pack_acc(v3.x, K2, M2, N1, C42, C32, C22, C12, C02, s0, s1);
        exp_pack_acc(v3.y, K2, M2, N1, C42, C32, C22, C12, C02, s2, s3);
        if (has5) {
            exp_pack_acc(v4.x, K2, M2, N1, C42, C32, C22, C12, C02, s0, s1);
            exp_pack_acc(v4.y, K2, M2, N1, C42, C32, C22, C12, C02, s2, s3);
        }

        float s = (s0 + s1) + (s2 + s3);
        #pragma unroll
        for (int o = 16; o > 0; o >>= 1)
            s += __shfl_down_sync(0xffffffffu, s, o);
        if (lane == 0) sh[warp] = s;
        __syncthreads();
        if (tid == 0) {
            float tot = 0.f;
            #pragma unroll
            for (int w = 0; w < 8; w++) tot += sh[w];
            g_pA[c] = tot;
        }
        p ^= 1;
        __syncthreads();
    }

    // ---------------- loop 2: small drain chunks (8KB) --------------------
    while (true) {
        const unsigned c = sh_tk[p];
        if (c >= NTICK) break;
        if (tid == 0) sh_tk[p ^ 1] = atomicAdd(&g_ticket, 1u);

        const unsigned ci = c - NBIG;
        const ulonglong2* __restrict__ base =
            (const ulonglong2*)logits + BIG_TOTAL_F4 + (size_t)ci * F4_SMALL;

        ulonglong2 v0 = base[tid];
        ulonglong2 v1;
        if (has2s) v1 = base[tid + 256];

        float s0 = 0.f, s1 = 0.f, s2 = 0.f, s3 = 0.f;
        exp_pack_acc(v0.x, K2, M2, N1, C42, C32, C22, C12, C02, s0, s1);
        exp_pack_acc(v0.y, K2, M2, N1, C42, C32, C22, C12, C02, s2, s3);
        if (has2s) {
            exp_pack_acc(v1.x, K2, M2, N1, C42, C32, C22, C12, C02, s0, s1);
            exp_pack_acc(v1.y, K2, M2, N1, C42, C32, C22, C12, C02, s2, s3);
        }

        float s = (s0 + s1) + (s2 + s3);
        #pragma unroll
        for (int o = 16; o > 0; o >>= 1)
            s += __shfl_down_sync(0xffffffffu, s, o);
        if (lane == 0) sh[warp] = s;
        __syncthreads();
        if (tid == 0) {
            float tot = 0.f;
            #pragma unroll
            for (int w = 0; w < 8; w++) tot += sh[w];
            g_pB[ci] = tot;
        }
        p ^= 1;
        __syncthreads();
    }

    // ---------------- join: last block runs the finish tail ---------------
    if (tid == 0) {
        __threadfence();                       // release my writes
        unsigned old = atomicAdd(&g_done, 1u);
        sh_last = (old == GRID_MAIN - 1) ? 1u : 0u;
    }
    __syncthreads();
    if (sh_last == 0) return;

    __threadfence();                           // acquire all blocks' writes
    __syncthreads();

    if (tid == 0) { g_ticket = 0; g_done = 0; }   // reset for graph replay

    float nll = 0.f;
    #pragma unroll
    for (int k = 0; k < 2; k++) {
        const int r = tid + k * 256;
        float a = 0.f, b = 0.f;
        if (r < ROWS_BIG) {
            const float* pp = g_pA + r * 20;
            #pragma unroll
            for (int s = 0; s < 20; s += 2) { a += pp[s]; b += pp[s + 1]; }
        } else {
            const float* pp = g_pB + (r - ROWS_BIG) * 50;
            #pragma unroll
            for (int s = 0; s < 50; s += 2) { a += pp[s]; b += pp[s + 1]; }
        }
        float sum = (a + b) + g_corr[r];
        nll += logf(sum) - g_smod[r];
    }

    float total = block_sum_256(nll, sh);
    if (tid == 0) out[0] = total * (1.0f / 512.0f);
}

extern "C" void kernel_launch(void* const* d_in, const int* in_sizes, int n_in,
                              void* d_out, int out_size) {
    const float* logits = (const float*)d_in[0];
    const float* norms = (const float*)d_in[1];
    const int* labels = (const int*)d_in[2];
    float* out = (float*)d_out;

    fused_kernel<<<GRID_MAIN, THREADS>>>(logits, norms, labels, out);
}

// round 16
// speedup vs baseline: 1.0702x; 1.0702x over previous
#include <cuda_runtime.h>
#include <math.h>

// ---------------------------------------------------------------------------
// AdaFaceLoss, single fused persistent kernel = R8 (best measured) with the
// ONE change: the global ticket is split into 8 per-group counters (256B
// apart -> distinct LTS slices) to break single-address atomic serialization
// (10240 same-address RMWs at ~5-8cyc each ~ the entire runtime).
//  - group g = bid & 7 steals within chunks [g*1280, (g+1)*1280).
//  - hot loop / barriers / preamble / join / tail identical to R8.
// Labels are int32 (JAX x64-disabled downgrades the int64 request).
// ---------------------------------------------------------------------------

#define B_ROWS 512
#define C_COLS 100000
#define F4_PER_CHUNK 1250            // 5000 floats = 20KB
#define CHUNKS_PER_ROW 20
#define NCHUNK (B_ROWS * CHUNKS_PER_ROW)   // 10240
#define THREADS 256
#define GRID_MAIN 1216               // 152 SMs * 8
#define NGROUP 8
#define CHUNKS_PER_GROUP (NCHUNK / NGROUP)   // 1280
#define TK_STRIDE 64                 // u32 stride -> 256B between counters

// exp(64*x) = 2^(K*x), K = 64*log2(e)
#define KLOG2 92.33248261689366f
#define MAGICF 12582912.0f           // 1.5 * 2^23
#define PC0 1.0f
#define PC1 0.6931471805599453f
#define PC2 0.2402265069591007f
#define PC3 0.05550410866482158f
#define PC4 0.009618129107628477f

__device__ float g_partials[NCHUNK];
__device__ float g_corr[B_ROWS];
__device__ float g_smod[B_ROWS];
__device__ unsigned g_tickets[NGROUP * TK_STRIDE];   // zero-init; last block resets
__device__ unsigned g_done;                          // last block resets

typedef unsigned long long u64;

// ---- packed f32x2 helpers (sm_103a) ----
__device__ __forceinline__ u64 pk2(float a, float b) {
    u64 r; asm("mov.b64 %0,{%1,%2};" : "=l"(r) : "f"(a), "f"(b)); return r;
}
__device__ __forceinline__ u64 mul2(u64 a, u64 b) {
    u64 r; asm("mul.rn.f32x2 %0,%1,%2;" : "=l"(r) : "l"(a), "l"(b)); return r;
}
__device__ __forceinline__ u64 add2(u64 a, u64 b) {
    u64 r; asm("add.rn.f32x2 %0,%1,%2;" : "=l"(r) : "l"(a), "l"(b)); return r;
}
__device__ __forceinline__ u64 fma2(u64 a, u64 b, u64 c) {
    u64 r; asm("fma.rn.f32x2 %0,%1,%2,%3;" : "=l"(r) : "l"(a), "l"(b), "l"(c)); return r;
}

// Scalar replica — bitwise-identical op sequence to the packed fast-exp so
// the label-column term cancels exactly.
__device__ __forceinline__ float fast_exp_scalar(float x) {
    float t = __fmul_rn(x, KLOG2);
    float z = __fadd_rn(t, MAGICF);
    float zn = __fmaf_rn(z, -1.0f, MAGICF);
    float f = __fmaf_rn(x, KLOG2, zn);
    float p = __fmaf_rn(PC4, f, PC3);
    p = __fmaf_rn(p, f, PC2);
    p = __fmaf_rn(p, f, PC1);
    p = __fmaf_rn(p, f, PC0);
    unsigned zi = __float_as_uint(z);
    return __uint_as_float(__float_as_uint(p) + (zi << 23));
}

__device__ __forceinline__ void exp_pack_acc(u64 x, u64 K2, u64 M2, u64 N1,
                                             u64 C42, u64 C32, u64 C22, u64 C12, u64 C02,
                                             float& a0, float& a1) {
    u64 t = mul2(x, K2);
    u64 z = add2(t, M2);
    u64 zn = fma2(z, N1, M2);        // -round(t)
    u64 f = fma2(x, K2, zn);
    u64 p = fma2(C42, f, C32);
    p = fma2(p, f, C22);
    p = fma2(p, f, C12);
    p = fma2(p, f, C02);
    unsigned zl = (unsigned)z, zh = (unsigned)(z >> 32);
    unsigned pl = (unsigned)p, ph = (unsigned)(p >> 32);
    a0 += __uint_as_float(pl + (zl << 23));
    a1 += __uint_as_float(ph + (zh << 23));
}

// block-wide sum over 256 threads; result broadcast
__device__ __forceinline__ float block_sum_256(float v, float* red) {
    #pragma unroll
    for (int o = 16; o > 0; o >>= 1)
        v += __shfl_down_sync(0xffffffffu, v, o);
    const int w = threadIdx.x >> 5;
    const int l = threadIdx.x & 31;
    if (l == 0) red[w] = v;
    __syncthreads();
    float t = 0.f;
    if (w == 0) {
        t = (l < 8) ? red[l] : 0.f;
        #pragma unroll
        for (int o = 4; o > 0; o >>= 1)
            t += __shfl_down_sync(0xffffffffu, t, o);
        if (l == 0) red[0] = t;
    }
    __syncthreads();
    float r = red[0];
    __syncthreads();
    return r;
}

__global__ __launch_bounds__(THREADS)
void fused_kernel(const float* __restrict__ logits,
                  const float* __restrict__ norms,
                  const int* __restrict__ labels,
                  float* __restrict__ out) {
    __shared__ float sh[8];
    __shared__ unsigned sh_tk[2];
    __shared__ unsigned sh_last;
    const int tid = threadIdx.x;
    const int warp = tid >> 5;
    const int lane = tid & 31;

    // ---------------- block 0: preamble, concurrent with streaming --------
    if (blockIdx.x == 0) {
        const int r0 = tid, r1 = tid + 256;
        int lab0 = labels[r0]; lab0 = max(0, min(lab0, C_COLS - 1));
        int lab1 = labels[r1]; lab1 = max(0, min(lab1, C_COLS - 1));
        const float x0 = __ldg(logits + (size_t)r0 * C_COLS + lab0);
        const float x1 = __ldg(logits + (size_t)r1 * C_COLS + lab1);

        float n0 = fminf(fmaxf(norms[r0], 0.001f), 100.0f);
        float n1 = fminf(fmaxf(norms[r1], 0.001f), 100.0f);
        float mean = block_sum_256(n0 + n1, sh) * (1.0f / 512.0f);
        float d0 = n0 - mean, d1 = n1 - mean;
        float var = block_sum_256(d0 * d0 + d1 * d1, sh) * (1.0f / 511.0f);
        float inv = 0.333f / (sqrtf(var) + 1e-6f);

        float ms0 = fminf(fmaxf((n0 - mean) * inv, -1.0f), 1.0f);
        float ms1 = fminf(fmaxf((n1 - mean) * inv, -1.0f), 1.0f);

        const float PI_EPS = 3.14159265358979323846f - 1e-6f;

        float c0 = fminf(fmaxf(x0, -1.0f + 1e-6f), 1.0f - 1e-6f);
        float th0 = fminf(fmaxf(acosf(c0) - 0.4f * ms0, 1e-6f), PI_EPS);
        float smod0 = (cosf(th0) - (0.4f + 0.4f * ms0)) * 64.0f;
        g_smod[r0] = smod0;
        g_corr[r0] = expf(smod0) - fast_exp_scalar(x0);

        float c1 = fminf(fmaxf(x1, -1.0f + 1e-6f), 1.0f - 1e-6f);
        float th1 = fminf(fmaxf(acosf(c1) - 0.4f * ms1, 1e-6f), PI_EPS);
        float smod1 = (cosf(th1) - (0.4f + 0.4f * ms1)) * 64.0f;
        g_smod[r1] = smod1;
        g_corr[r1] = expf(smod1) - fast_exp_scalar(x1);
        __syncthreads();
    }

    // ---------------- streaming: R8 core, per-group ticket ----------------
    const u64 K2 = pk2(KLOG2, KLOG2);
    const u64 M2 = pk2(MAGICF, MAGICF);
    const u64 N1 = pk2(-1.0f, -1.0f);
    const u64 C42 = pk2(PC4, PC4);
    const u64 C32 = pk2(PC3, PC3);
    const u64 C22 = pk2(PC2, PC2);
    const u64 C12 = pk2(PC1, PC1);
    const u64 C02 = pk2(PC0, PC0);

    unsigned* my_ticket = &g_tickets[(blockIdx.x & (NGROUP - 1)) * TK_STRIDE];
    const unsigned group_base = (blockIdx.x & (NGROUP - 1)) * CHUNKS_PER_GROUP;

    if (tid == 0) sh_tk[0] = atomicAdd(my_ticket, 1u);
    __syncthreads();

    const bool has5 = (tid + 1024) < F4_PER_CHUNK;   // tid < 226

    int p = 0;
    while (true) {
        const unsigned ci = sh_tk[p];
        if (ci >= CHUNKS_PER_GROUP) break;
        const unsigned c = group_base + ci;
        // prefetch next ticket; its latency hides under this chunk's loads
        if (tid == 0) sh_tk[p ^ 1] = atomicAdd(my_ticket, 1u);

        const ulonglong2* __restrict__ base =
            (const ulonglong2*)logits + (size_t)c * F4_PER_CHUNK;

        ulonglong2 v0 = base[tid];
        ulonglong2 v1 = base[tid + 256];
        ulonglong2 v2 = base[tid + 512];
        ulonglong2 v3 = base[tid + 768];
        ulonglong2 v4;
        if (has5) v4 = base[tid + 1024];

        float s0 = 0.f, s1 = 0.f, s2 = 0.f, s3 = 0.f;
        exp_pack_acc(v0.x, K2, M2, N1, C42, C32, C22, C12, C02, s0, s1);
        exp_pack_acc(v0.y, K2, M2, N1, C42, C32, C22, C12, C02, s2, s3);
        exp_pack_acc(v1.x, K2, M2, N1, C42, C32, C22, C12, C02, s0, s1);
        exp_pack_acc(v1.y, K2, M2, N1, C42, C32, C22, C12, C02, s2, s3);
        exp_pack_acc(v2.x, K2, M2, N1, C42, C32, C22, C12, C02, s0, s1);
        exp_pack_acc(v2.y, K2, M2, N1, C42, C32, C22, C12, C02, s2, s3);
        exp_pack_acc(v3.x, K2, M2, N1, C42, C32, C22, C12, C02, s0, s1);
        exp_pack_acc(v3.y, K2, M2, N1, C42, C32, C22, C12, C02, s2, s3);
        if (has5) {
            exp_pack_acc(v4.x, K2, M2, N1, C42, C32, C22, C12, C02, s0, s1);
            exp_pack_acc(v4.y, K2, M2, N1, C42, C32, C22, C12, C02, s2, s3);
        }

        float s = (s0 + s1) + (s2 + s3);
        #pragma unroll
        for (int o = 16; o > 0; o >>= 1)
            s += __shfl_down_sync(0xffffffffu, s, o);
        if (lane == 0) sh[warp] = s;
        __syncthreads();
        if (tid == 0) {
            float tot = 0.f;
            #pragma unroll
            for (int w = 0; w < 8; w++) tot += sh[w];
            g_partials[c] = tot;
        }
        p ^= 1;
        __syncthreads();
    }

    // ---------------- join: last block runs the finish tail ---------------
    if (tid == 0) {
        __threadfence();                       // release my writes
        unsigned old = atomicAdd(&g_done, 1u);
        sh_last = (old == GRID_MAIN - 1) ? 1u : 0u;
    }
    __syncthreads();
    if (sh_last == 0) return;

    __threadfence();                           // acquire all blocks' writes
    __syncthreads();

    if (tid < NGROUP) g_tickets[tid * TK_STRIDE] = 0;   // reset for replay
    if (tid == 0) g_done = 0;

    const int r0 = tid, r1 = tid + 256;
    const float* pp0 = g_partials + (size_t)r0 * CHUNKS_PER_ROW;
    const float* pp1 = g_partials + (size_t)r1 * CHUNKS_PER_ROW;
    float a0 = 0.f, a1 = 0.f, b0 = 0.f, b1 = 0.f;
    #pragma unroll
    for (int s = 0; s < CHUNKS_PER_ROW; s += 2) {
        a0 += pp0[s];
        a1 += pp0[s + 1];
        b0 += pp1[s];
        b1 += pp1[s + 1];
    }
    float sum0 = (a0 + a1) + g_corr[r0];
    float sum1 = (b0 + b1) + g_corr[r1];

    float nll = (logf(sum0) - g_smod[r0]) + (logf(sum1) - g_smod[r1]);

    float total = block_sum_256(nll, sh);
    if (tid == 0) out[0] = total * (1.0f / 512.0f);
}

extern "C" void kernel_launch(void* const* d_in, const int* in_sizes, int n_in,
                              void* d_out, int out_size) {
    const float* logits = (const float*)d_in[0];
    const float* norms = (const float*)d_in[1];
    const int* labels = (const int*)d_in[2];
    float* out = (float*)d_out;

    fused_kernel<<<GRID_MAIN, THREADS>>>(logits, norms, labels, out);
}